// round 1
// baseline (speedup 1.0000x reference)
#include <cuda_runtime.h>

#define NN 50000
#define EEMAX 800000

// ---------------- scratch (static device globals; no allocation) -------------
__device__ float g_in0[NN * 128];    // layer-0 input: concat(x, template emb)
__device__ float g_feat[NN * 256];   // per-layer linear output h
__device__ float g_out[NN * 256];    // per-layer aggregated output
__device__ float g_ssrc[NN * 4];
__device__ float g_sdst[NN * 4];
__device__ float g_m[NN * 4];        // segment max
__device__ float g_den[NN * 4];      // segment sum of exp

__device__ __forceinline__ float lrelu(float x, float s) { return x >= 0.f ? x : s * x; }

__device__ __forceinline__ void atomicMaxFloat(float* addr, float v) {
    if (v >= 0.f) atomicMax((int*)addr, __float_as_int(v));
    else          atomicMin((unsigned int*)addr, __float_as_uint(v));
}

__device__ __forceinline__ void edge_sd(const int* __restrict__ ei, int e, int E, int& s, int& d) {
    if (e < E) { s = ei[e]; d = ei[E + e]; }
    else       { s = e - E; d = e - E; }   // appended self-loops
}

// ---------------- layer-0 input build: in0 = [x | emb[class_label[batch]]] ---
__global__ void build_in0_kernel(const float* __restrict__ x,
                                 const int* __restrict__ batch,
                                 const int* __restrict__ clab,
                                 const float* __restrict__ emb, int n) {
    int gt = blockIdx.x * blockDim.x + threadIdx.x;
    int node = gt >> 5, lane = gt & 31;
    if (node >= n) return;
    float4* dst = reinterpret_cast<float4*>(g_in0 + (size_t)node * 128);
    if (lane < 16) {
        dst[lane] = reinterpret_cast<const float4*>(x + (size_t)node * 64)[lane];
    } else {
        int c = clab[batch[node]];
        dst[lane] = reinterpret_cast<const float4*>(emb + (size_t)c * 64)[lane - 16];
    }
}

// ---------------- GEMM: g_feat[M,256] = act(A[M,K]) @ W[256,K]^T -------------
// BM=128, BN=64, BK=32, 256 threads, 8x4 micro-tile per thread.
// SRC: 0 -> g_in0, 1 -> g_out. ACT applies leaky_relu(0.01) to the A operand.
template <int K, bool ACT, int SRC>
__global__ void __launch_bounds__(256) gemm_kernel(const float* __restrict__ Wm, int M) {
    __shared__ float As[32][129];
    __shared__ float Ws[32][65];
    const float* __restrict__ A = (SRC == 0) ? g_in0 : g_out;

    const int tid = threadIdx.x;
    const int tx = tid & 15, ty = tid >> 4;
    const int rowBase = blockIdx.x * 128;
    const int colBase = blockIdx.y * 64;

    float acc[8][4];
#pragma unroll
    for (int i = 0; i < 8; i++)
#pragma unroll
        for (int j = 0; j < 4; j++) acc[i][j] = 0.f;

    for (int k0 = 0; k0 < K; k0 += 32) {
        // A tile: 128x32 floats = 1024 float4, 4 per thread
#pragma unroll
        for (int i = 0; i < 4; i++) {
            int f = tid + i * 256;
            int r = f >> 3, c4 = f & 7;
            float4 v = make_float4(0.f, 0.f, 0.f, 0.f);
            int gr = rowBase + r;
            if (gr < M) v = *reinterpret_cast<const float4*>(A + (size_t)gr * K + k0 + c4 * 4);
            if (ACT) {
                v.x = lrelu(v.x, 0.01f); v.y = lrelu(v.y, 0.01f);
                v.z = lrelu(v.z, 0.01f); v.w = lrelu(v.w, 0.01f);
            }
            As[c4 * 4 + 0][r] = v.x; As[c4 * 4 + 1][r] = v.y;
            As[c4 * 4 + 2][r] = v.z; As[c4 * 4 + 3][r] = v.w;
        }
        // W tile: 64x32 floats = 512 float4, 2 per thread
#pragma unroll
        for (int i = 0; i < 2; i++) {
            int f = tid + i * 256;
            int r = f >> 3, c4 = f & 7;
            float4 v = *reinterpret_cast<const float4*>(Wm + (size_t)(colBase + r) * K + k0 + c4 * 4);
            Ws[c4 * 4 + 0][r] = v.x; Ws[c4 * 4 + 1][r] = v.y;
            Ws[c4 * 4 + 2][r] = v.z; Ws[c4 * 4 + 3][r] = v.w;
        }
        __syncthreads();
#pragma unroll
        for (int k = 0; k < 32; k++) {
            float a[8], bb[4];
#pragma unroll
            for (int i = 0; i < 8; i++) a[i] = As[k][ty * 8 + i];
#pragma unroll
            for (int j = 0; j < 4; j++) bb[j] = Ws[k][tx * 4 + j];
#pragma unroll
            for (int i = 0; i < 8; i++)
#pragma unroll
                for (int j = 0; j < 4; j++)
                    acc[i][j] = fmaf(a[i], bb[j], acc[i][j]);
        }
        __syncthreads();
    }
#pragma unroll
    for (int i = 0; i < 8; i++) {
        int r = rowBase + ty * 8 + i;
        if (r < M) {
            float4 v = make_float4(acc[i][0], acc[i][1], acc[i][2], acc[i][3]);
            *reinterpret_cast<float4*>(g_feat + (size_t)r * 256 + colBase + tx * 4) = v;
        }
    }
}

// ---------------- per-node attention scores ---------------------------------
// warp per node; lane covers 8 consecutive dims (one head per 8-lane group)
__global__ void s_kernel(const float* __restrict__ asrc, const float* __restrict__ adst, int n) {
    int gt = blockIdx.x * blockDim.x + threadIdx.x;
    int node = gt >> 5, lane = gt & 31;
    if (node >= n) return;
    const float4* f4 = reinterpret_cast<const float4*>(g_feat + (size_t)node * 256 + lane * 8);
    const float4* a4 = reinterpret_cast<const float4*>(asrc + lane * 8);
    const float4* d4 = reinterpret_cast<const float4*>(adst + lane * 8);
    float ss = 0.f, sd = 0.f;
#pragma unroll
    for (int i = 0; i < 2; i++) {
        float4 h = f4[i], va = a4[i], vd = d4[i];
        ss += h.x * va.x + h.y * va.y + h.z * va.z + h.w * va.w;
        sd += h.x * vd.x + h.y * vd.y + h.z * vd.z + h.w * vd.w;
    }
#pragma unroll
    for (int off = 4; off; off >>= 1) {
        ss += __shfl_xor_sync(0xffffffffu, ss, off);
        sd += __shfl_xor_sync(0xffffffffu, sd, off);
    }
    if ((lane & 7) == 0) {
        g_ssrc[node * 4 + (lane >> 3)] = ss;
        g_sdst[node * 4 + (lane >> 3)] = sd;
    }
}

// ---------------- init: out = bias, m = -inf, den = 0 -----------------------
__global__ void init_kernel(const float* __restrict__ b, int n) {
    int idx = blockIdx.x * blockDim.x + threadIdx.x;
    if (idx < n * 256) g_out[idx] = b[idx & 255];
    if (idx < n * 4) {
        g_m[idx] = __int_as_float(0xff800000);  // -inf
        g_den[idx] = 0.f;
    }
}

// ---------------- edge pass 1: segment max of alpha --------------------------
__global__ void pass1_kernel(const int* __restrict__ ei, int E, int ET) {
    int e = blockIdx.x * blockDim.x + threadIdx.x;
    if (e >= ET) return;
    int s, d; edge_sd(ei, e, E, s, d);
    float4 ss = *reinterpret_cast<const float4*>(g_ssrc + (size_t)s * 4);
    float4 sd = *reinterpret_cast<const float4*>(g_sdst + (size_t)d * 4);
    float* mp = g_m + (size_t)d * 4;
    atomicMaxFloat(mp + 0, lrelu(ss.x + sd.x, 0.2f));
    atomicMaxFloat(mp + 1, lrelu(ss.y + sd.y, 0.2f));
    atomicMaxFloat(mp + 2, lrelu(ss.z + sd.z, 0.2f));
    atomicMaxFloat(mp + 3, lrelu(ss.w + sd.w, 0.2f));
}

// ---------------- edge pass 2: segment sum of exp(alpha - m) -----------------
__global__ void pass2_kernel(const int* __restrict__ ei, int E, int ET) {
    int e = blockIdx.x * blockDim.x + threadIdx.x;
    if (e >= ET) return;
    int s, d; edge_sd(ei, e, E, s, d);
    float4 ss = *reinterpret_cast<const float4*>(g_ssrc + (size_t)s * 4);
    float4 sd = *reinterpret_cast<const float4*>(g_sdst + (size_t)d * 4);
    float4 mm = *reinterpret_cast<const float4*>(g_m + (size_t)d * 4);
    float4 ex;
    ex.x = __expf(lrelu(ss.x + sd.x, 0.2f) - mm.x);
    ex.y = __expf(lrelu(ss.y + sd.y, 0.2f) - mm.y);
    ex.z = __expf(lrelu(ss.z + sd.z, 0.2f) - mm.z);
    ex.w = __expf(lrelu(ss.w + sd.w, 0.2f) - mm.w);
    atomicAdd(reinterpret_cast<float4*>(g_den + (size_t)d * 4), ex);
}

// ---------------- edge pass 3: weighted aggregation (warp per edge) ----------
__global__ void pass3_kernel(const int* __restrict__ ei, int E, int ET) {
    int gt = blockIdx.x * blockDim.x + threadIdx.x;
    int e = gt >> 5, lane = gt & 31;
    if (e >= ET) return;
    int s, d; edge_sd(ei, e, E, s, d);
    int h = lane >> 3;
    float a = lrelu(g_ssrc[(size_t)s * 4 + h] + g_sdst[(size_t)d * 4 + h], 0.2f);
    float ex = __expf(a - g_m[(size_t)d * 4 + h]);
    float w = ex / (g_den[(size_t)d * 4 + h] + 1e-16f);
    const float4* hv = reinterpret_cast<const float4*>(g_feat + (size_t)s * 256 + lane * 8);
    float4* op = reinterpret_cast<float4*>(g_out + (size_t)d * 256 + lane * 8);
#pragma unroll
    for (int i = 0; i < 2; i++) {
        float4 v = hv[i];
        v.x *= w; v.y *= w; v.z *= w; v.w *= w;
        atomicAdd(op + i, v);   // red.global.v4.f32 on sm_90+
    }
}

// ---------------- classifier: y[n] = lrelu(out[n]) . clsW + clsb -------------
__global__ void cls_kernel(const float* __restrict__ clsW, const float* __restrict__ clsb,
                           float* __restrict__ y, int n) {
    int gt = blockIdx.x * blockDim.x + threadIdx.x;
    int node = gt >> 5, lane = gt & 31;
    if (node >= n) return;
    const float4* o4 = reinterpret_cast<const float4*>(g_out + (size_t)node * 256 + lane * 8);
    const float4* w4 = reinterpret_cast<const float4*>(clsW + lane * 8);
    float sum = 0.f;
#pragma unroll
    for (int i = 0; i < 2; i++) {
        float4 v = o4[i], w = w4[i];
        sum += lrelu(v.x, 0.01f) * w.x + lrelu(v.y, 0.01f) * w.y +
               lrelu(v.z, 0.01f) * w.z + lrelu(v.w, 0.01f) * w.w;
    }
#pragma unroll
    for (int off = 16; off; off >>= 1) sum += __shfl_xor_sync(0xffffffffu, sum, off);
    if (lane == 0) y[node] = sum + clsb[0];
}

static inline int cdiv(int a, int b) { return (a + b - 1) / b; }

extern "C" void kernel_launch(void* const* d_in, const int* in_sizes, int n_in,
                              void* d_out, int out_size) {
    const float* x     = (const float*)d_in[0];
    const int*   ei    = (const int*)d_in[1];
    const int*   batch = (const int*)d_in[2];
    const int*   clab  = (const int*)d_in[3];
    const float* emb   = (const float*)d_in[4];
    const float* W0    = (const float*)d_in[5];
    const float* as0   = (const float*)d_in[6];
    const float* ad0   = (const float*)d_in[7];
    const float* b0    = (const float*)d_in[8];
    const float* W1    = (const float*)d_in[9];
    const float* as1   = (const float*)d_in[10];
    const float* ad1   = (const float*)d_in[11];
    const float* b1    = (const float*)d_in[12];
    const float* W2    = (const float*)d_in[13];
    const float* as2   = (const float*)d_in[14];
    const float* ad2   = (const float*)d_in[15];
    const float* b2    = (const float*)d_in[16];
    const float* clsW  = (const float*)d_in[17];
    const float* clsb  = (const float*)d_in[18];

    int n  = in_sizes[0] / 64;   // 50000
    int E  = in_sizes[1] / 2;    // 800000
    int ET = E + n;              // with self-loops

    const int T = 256;
    int warpBlocks = cdiv(n * 32, T);

    build_in0_kernel<<<warpBlocks, T>>>(x, batch, clab, emb, n);

    dim3 gemm_grid(cdiv(n, 128), 4);

    const float* asl[3] = {as0, as1, as2};
    const float* adl[3] = {ad0, ad1, ad2};
    const float* bl[3]  = {b0, b1, b2};

    for (int l = 0; l < 3; l++) {
        if (l == 0)      gemm_kernel<128, false, 0><<<gemm_grid, T>>>(W0, n);
        else if (l == 1) gemm_kernel<256, true, 1><<<gemm_grid, T>>>(W1, n);
        else             gemm_kernel<256, true, 1><<<gemm_grid, T>>>(W2, n);

        s_kernel<<<warpBlocks, T>>>(asl[l], adl[l], n);
        init_kernel<<<cdiv(n * 256, T), T>>>(bl[l], n);
        pass1_kernel<<<cdiv(ET, T), T>>>(ei, E, ET);
        pass2_kernel<<<cdiv(ET, T), T>>>(ei, E, ET);
        pass3_kernel<<<cdiv(ET * 32, T), T>>>(ei, E, ET);
    }

    cls_kernel<<<warpBlocks, T>>>(clsW, clsb, (float*)d_out, n);
}

// round 2
// speedup vs baseline: 2.8851x; 2.8851x over previous
#include <cuda_runtime.h>
#include <cstdint>

#define NN 50000
#define EEMAX 800000

// ---------------- scratch (static device globals; no allocation) -------------
__device__ float g_in0[NN * 128];
__device__ float g_feat[NN * 256];
__device__ float g_out[NN * 256];
__device__ float g_ssrc[NN * 4];
__device__ float g_sdst[NN * 4];
__device__ int   g_deg[NN];
__device__ int   g_cursor[NN];
__device__ int   g_rowptr[NN + 1];
__device__ int   g_csrc[EEMAX + NN];
__device__ int   g_bsum[256];
__device__ int   g_bpre[257];

__device__ __forceinline__ float lrelu(float x, float s) { return x >= 0.f ? x : s * x; }

__device__ __forceinline__ uint32_t f2tf32(float f) {
    uint32_t r;
    asm("cvt.rna.tf32.f32 %0, %1;" : "=r"(r) : "f"(f));
    return r;
}

__device__ __forceinline__ void mma_tf32(float4& c, const uint32_t a[4], const uint32_t b[2]) {
    asm volatile(
        "mma.sync.aligned.m16n8k8.row.col.f32.tf32.tf32.f32 "
        "{%0,%1,%2,%3}, {%4,%5,%6,%7}, {%8,%9}, {%0,%1,%2,%3};"
        : "+f"(c.x), "+f"(c.y), "+f"(c.z), "+f"(c.w)
        : "r"(a[0]), "r"(a[1]), "r"(a[2]), "r"(a[3]), "r"(b[0]), "r"(b[1]));
}

__device__ __forceinline__ void edge_sd(const int* __restrict__ ei, int e, int E, int& s, int& d) {
    if (e < E) { s = ei[e]; d = ei[E + e]; }
    else       { s = e - E; d = e - E; }   // appended self-loops
}

// ---------------- layer-0 input build: in0 = [x | emb[class_label[batch]]] ---
__global__ void build_in0_kernel(const float* __restrict__ x,
                                 const int* __restrict__ batch,
                                 const int* __restrict__ clab,
                                 const float* __restrict__ emb, int n) {
    int gt = blockIdx.x * blockDim.x + threadIdx.x;
    int node = gt >> 5, lane = gt & 31;
    if (node >= n) return;
    float4* dst = reinterpret_cast<float4*>(g_in0 + (size_t)node * 128);
    if (lane < 16) {
        dst[lane] = reinterpret_cast<const float4*>(x + (size_t)node * 64)[lane];
    } else {
        int c = clab[batch[node]];
        dst[lane] = reinterpret_cast<const float4*>(emb + (size_t)c * 64)[lane - 16];
    }
}

// ---------------- tensor-core GEMM: g_feat = act(A[M,K]) @ W[256,K]^T --------
// BM=128, BN=128, BK=32, 256 threads = 8 warps (4x2), warp tile 32x64,
// mma.sync m16n8k8 tf32 with fp32 accumulate.
template <int K, bool ACT, int SRC>
__global__ void __launch_bounds__(256, 2) gemm_tc_kernel(const float* __restrict__ Wm, int M) {
    __shared__ uint32_t As[128][36];
    __shared__ uint32_t Bs[128][36];
    const float* __restrict__ A = (SRC == 0) ? g_in0 : g_out;

    const int tid = threadIdx.x;
    const int warp = tid >> 5, lane = tid & 31;
    const int wm = warp >> 1;          // 0..3
    const int wn = warp & 1;           // 0..1
    const int rowBase = blockIdx.x * 128;
    const int colBase = blockIdx.y * 128;

    float4 c[2][8];
#pragma unroll
    for (int i = 0; i < 2; i++)
#pragma unroll
        for (int j = 0; j < 8; j++) c[i][j] = make_float4(0.f, 0.f, 0.f, 0.f);

    for (int k0 = 0; k0 < K; k0 += 32) {
        // A tile: 128x32 floats = 1024 float4, 4 per thread
#pragma unroll
        for (int i = 0; i < 4; i++) {
            int f = tid + i * 256;
            int r = f >> 3, c4 = f & 7;
            float4 v = make_float4(0.f, 0.f, 0.f, 0.f);
            int gr = rowBase + r;
            if (gr < M) v = *reinterpret_cast<const float4*>(A + (size_t)gr * K + k0 + c4 * 4);
            if (ACT) {
                v.x = lrelu(v.x, 0.01f); v.y = lrelu(v.y, 0.01f);
                v.z = lrelu(v.z, 0.01f); v.w = lrelu(v.w, 0.01f);
            }
            uint4 t = make_uint4(f2tf32(v.x), f2tf32(v.y), f2tf32(v.z), f2tf32(v.w));
            *reinterpret_cast<uint4*>(&As[r][c4 * 4]) = t;
        }
        // B tile: W rows [colBase, colBase+128), 128x32 floats
#pragma unroll
        for (int i = 0; i < 4; i++) {
            int f = tid + i * 256;
            int r = f >> 3, c4 = f & 7;
            float4 v = *reinterpret_cast<const float4*>(Wm + (size_t)(colBase + r) * K + k0 + c4 * 4);
            uint4 t = make_uint4(f2tf32(v.x), f2tf32(v.y), f2tf32(v.z), f2tf32(v.w));
            *reinterpret_cast<uint4*>(&Bs[r][c4 * 4]) = t;
        }
        __syncthreads();
#pragma unroll
        for (int ks = 0; ks < 4; ks++) {
            const int kc = ks * 8 + (lane & 3);
            uint32_t bfr[8][2];
#pragma unroll
            for (int j = 0; j < 8; j++) {
                int cn = wn * 64 + j * 8 + (lane >> 2);
                bfr[j][0] = Bs[cn][kc];
                bfr[j][1] = Bs[cn][kc + 4];
            }
            uint32_t afr[2][4];
#pragma unroll
            for (int i = 0; i < 2; i++) {
                int r = wm * 32 + i * 16 + (lane >> 2);
                afr[i][0] = As[r][kc];
                afr[i][1] = As[r + 8][kc];
                afr[i][2] = As[r][kc + 4];
                afr[i][3] = As[r + 8][kc + 4];
            }
#pragma unroll
            for (int i = 0; i < 2; i++)
#pragma unroll
                for (int j = 0; j < 8; j++) mma_tf32(c[i][j], afr[i], bfr[j]);
        }
        __syncthreads();
    }

    // epilogue: C frag layout -> g_feat[M,256]
#pragma unroll
    for (int i = 0; i < 2; i++) {
#pragma unroll
        for (int j = 0; j < 8; j++) {
            int row0 = rowBase + wm * 32 + i * 16 + (lane >> 2);
            int coln = colBase + wn * 64 + j * 8 + 2 * (lane & 3);
            if (row0 < M)
                *reinterpret_cast<float2*>(g_feat + (size_t)row0 * 256 + coln) =
                    make_float2(c[i][j].x, c[i][j].y);
            if (row0 + 8 < M)
                *reinterpret_cast<float2*>(g_feat + (size_t)(row0 + 8) * 256 + coln) =
                    make_float2(c[i][j].z, c[i][j].w);
        }
    }
}

// ---------------- per-node attention scores ---------------------------------
__global__ void s_kernel(const float* __restrict__ asrc, const float* __restrict__ adst, int n) {
    int gt = blockIdx.x * blockDim.x + threadIdx.x;
    int node = gt >> 5, lane = gt & 31;
    if (node >= n) return;
    const float4* f4 = reinterpret_cast<const float4*>(g_feat + (size_t)node * 256 + lane * 8);
    const float4* a4 = reinterpret_cast<const float4*>(asrc + lane * 8);
    const float4* d4 = reinterpret_cast<const float4*>(adst + lane * 8);
    float ss = 0.f, sd = 0.f;
#pragma unroll
    for (int i = 0; i < 2; i++) {
        float4 h = f4[i], va = a4[i], vd = d4[i];
        ss += h.x * va.x + h.y * va.y + h.z * va.z + h.w * va.w;
        sd += h.x * vd.x + h.y * vd.y + h.z * vd.z + h.w * vd.w;
    }
#pragma unroll
    for (int off = 4; off; off >>= 1) {
        ss += __shfl_xor_sync(0xffffffffu, ss, off);
        sd += __shfl_xor_sync(0xffffffffu, sd, off);
    }
    if ((lane & 7) == 0) {
        g_ssrc[node * 4 + (lane >> 3)] = ss;
        g_sdst[node * 4 + (lane >> 3)] = sd;
    }
}

// ---------------- CSR build --------------------------------------------------
__global__ void zero_kernel(int n) {
    int i = blockIdx.x * blockDim.x + threadIdx.x;
    if (i < n) { g_deg[i] = 0; g_cursor[i] = 0; }
}

__global__ void deg_kernel(const int* __restrict__ ei, int E, int ET) {
    int e = blockIdx.x * blockDim.x + threadIdx.x;
    if (e >= ET) return;
    int s, d; edge_sd(ei, e, E, s, d);
    atomicAdd(&g_deg[d], 1);
}

__global__ void scan1_kernel(int n) {
    __shared__ int sh[512];
    int i = blockIdx.x * 512 + threadIdx.x;
    int v = (i < n) ? g_deg[i] : 0;
    sh[threadIdx.x] = v;
    __syncthreads();
#pragma unroll
    for (int off = 1; off < 512; off <<= 1) {
        int t = (threadIdx.x >= off) ? sh[threadIdx.x - off] : 0;
        __syncthreads();
        if (threadIdx.x >= off) sh[threadIdx.x] += t;
        __syncthreads();
    }
    if (i < n) g_rowptr[i] = sh[threadIdx.x] - v;  // exclusive within block
    if (threadIdx.x == 511) g_bsum[blockIdx.x] = sh[511];
}

__global__ void scan2_kernel(int nb, int n) {
    if (threadIdx.x == 0 && blockIdx.x == 0) {
        int acc = 0;
        for (int j = 0; j < nb; j++) { g_bpre[j] = acc; acc += g_bsum[j]; }
        g_rowptr[n] = acc;
    }
}

__global__ void scan3_kernel(int n) {
    int i = blockIdx.x * 512 + threadIdx.x;
    if (i < n) g_rowptr[i] += g_bpre[blockIdx.x];
}

__global__ void scatter_kernel(const int* __restrict__ ei, int E, int ET) {
    int e = blockIdx.x * blockDim.x + threadIdx.x;
    if (e >= ET) return;
    int s, d; edge_sd(ei, e, E, s, d);
    int pos = g_rowptr[d] + atomicAdd(&g_cursor[d], 1);
    g_csrc[pos] = s;
}

// ---------------- fused softmax + aggregation: warp per dst ------------------
__global__ void agg_kernel(const float* __restrict__ b, int n) {
    int gt = blockIdx.x * blockDim.x + threadIdx.x;
    int dst = gt >> 5, lane = gt & 31;
    if (dst >= n) return;
    const int beg = g_rowptr[dst], end = g_rowptr[dst + 1];
    const float4 sd4 = *reinterpret_cast<const float4*>(g_sdst + (size_t)dst * 4);

    // phase 1: segment max per head
    const float NEG = __int_as_float(0xff800000);
    float4 mx = make_float4(NEG, NEG, NEG, NEG);
    for (int i = beg + lane; i < end; i += 32) {
        int s = g_csrc[i];
        float4 ss = *reinterpret_cast<const float4*>(g_ssrc + (size_t)s * 4);
        mx.x = fmaxf(mx.x, lrelu(ss.x + sd4.x, 0.2f));
        mx.y = fmaxf(mx.y, lrelu(ss.y + sd4.y, 0.2f));
        mx.z = fmaxf(mx.z, lrelu(ss.z + sd4.z, 0.2f));
        mx.w = fmaxf(mx.w, lrelu(ss.w + sd4.w, 0.2f));
    }
#pragma unroll
    for (int off = 16; off; off >>= 1) {
        mx.x = fmaxf(mx.x, __shfl_xor_sync(0xffffffffu, mx.x, off));
        mx.y = fmaxf(mx.y, __shfl_xor_sync(0xffffffffu, mx.y, off));
        mx.z = fmaxf(mx.z, __shfl_xor_sync(0xffffffffu, mx.z, off));
        mx.w = fmaxf(mx.w, __shfl_xor_sync(0xffffffffu, mx.w, off));
    }

    // phase 2: segment sum of exp
    float4 den = make_float4(0.f, 0.f, 0.f, 0.f);
    for (int i = beg + lane; i < end; i += 32) {
        int s = g_csrc[i];
        float4 ss = *reinterpret_cast<const float4*>(g_ssrc + (size_t)s * 4);
        den.x += __expf(lrelu(ss.x + sd4.x, 0.2f) - mx.x);
        den.y += __expf(lrelu(ss.y + sd4.y, 0.2f) - mx.y);
        den.z += __expf(lrelu(ss.z + sd4.z, 0.2f) - mx.z);
        den.w += __expf(lrelu(ss.w + sd4.w, 0.2f) - mx.w);
    }
#pragma unroll
    for (int off = 16; off; off >>= 1) {
        den.x += __shfl_xor_sync(0xffffffffu, den.x, off);
        den.y += __shfl_xor_sync(0xffffffffu, den.y, off);
        den.z += __shfl_xor_sync(0xffffffffu, den.z, off);
        den.w += __shfl_xor_sync(0xffffffffu, den.w, off);
    }

    // per-lane head selections
    const int h = lane >> 3;
    float mh  = (h & 2) ? ((h & 1) ? mx.w : mx.z) : ((h & 1) ? mx.y : mx.x);
    float dh  = (h & 2) ? ((h & 1) ? den.w : den.z) : ((h & 1) ? den.y : den.x);
    float sdh = (h & 2) ? ((h & 1) ? sd4.w : sd4.z) : ((h & 1) ? sd4.y : sd4.x);
    const float invd = 1.f / (dh + 1e-16f);

    // phase 3: weighted aggregation (warp cooperates on 256-wide vector)
    float4 acc0 = make_float4(0.f, 0.f, 0.f, 0.f);
    float4 acc1 = make_float4(0.f, 0.f, 0.f, 0.f);
    for (int i = beg; i < end; i++) {
        int s = g_csrc[i];
        float w = __expf(lrelu(g_ssrc[(size_t)s * 4 + h] + sdh, 0.2f) - mh) * invd;
        const float4* hv = reinterpret_cast<const float4*>(g_feat + (size_t)s * 256 + lane * 8);
        float4 v0 = hv[0], v1 = hv[1];
        acc0.x += w * v0.x; acc0.y += w * v0.y; acc0.z += w * v0.z; acc0.w += w * v0.w;
        acc1.x += w * v1.x; acc1.y += w * v1.y; acc1.z += w * v1.z; acc1.w += w * v1.w;
    }
    const float4 b0 = reinterpret_cast<const float4*>(b)[lane * 2];
    const float4 b1 = reinterpret_cast<const float4*>(b)[lane * 2 + 1];
    float4* op = reinterpret_cast<float4*>(g_out + (size_t)dst * 256 + lane * 8);
    op[0] = make_float4(acc0.x + b0.x, acc0.y + b0.y, acc0.z + b0.z, acc0.w + b0.w);
    op[1] = make_float4(acc1.x + b1.x, acc1.y + b1.y, acc1.z + b1.z, acc1.w + b1.w);
}

// ---------------- classifier -------------------------------------------------
__global__ void cls_kernel(const float* __restrict__ clsW, const float* __restrict__ clsb,
                           float* __restrict__ y, int n) {
    int gt = blockIdx.x * blockDim.x + threadIdx.x;
    int node = gt >> 5, lane = gt & 31;
    if (node >= n) return;
    const float4* o4 = reinterpret_cast<const float4*>(g_out + (size_t)node * 256 + lane * 8);
    const float4* w4 = reinterpret_cast<const float4*>(clsW + lane * 8);
    float sum = 0.f;
#pragma unroll
    for (int i = 0; i < 2; i++) {
        float4 v = o4[i], w = w4[i];
        sum += lrelu(v.x, 0.01f) * w.x + lrelu(v.y, 0.01f) * w.y +
               lrelu(v.z, 0.01f) * w.z + lrelu(v.w, 0.01f) * w.w;
    }
#pragma unroll
    for (int off = 16; off; off >>= 1) sum += __shfl_xor_sync(0xffffffffu, sum, off);
    if (lane == 0) y[node] = sum + clsb[0];
}

static inline int cdiv(int a, int b) { return (a + b - 1) / b; }

extern "C" void kernel_launch(void* const* d_in, const int* in_sizes, int n_in,
                              void* d_out, int out_size) {
    const float* x     = (const float*)d_in[0];
    const int*   ei    = (const int*)d_in[1];
    const int*   batch = (const int*)d_in[2];
    const int*   clab  = (const int*)d_in[3];
    const float* emb   = (const float*)d_in[4];
    const float* W0    = (const float*)d_in[5];
    const float* as0   = (const float*)d_in[6];
    const float* ad0   = (const float*)d_in[7];
    const float* b0    = (const float*)d_in[8];
    const float* W1    = (const float*)d_in[9];
    const float* as1   = (const float*)d_in[10];
    const float* ad1   = (const float*)d_in[11];
    const float* b1    = (const float*)d_in[12];
    const float* W2    = (const float*)d_in[13];
    const float* as2   = (const float*)d_in[14];
    const float* ad2   = (const float*)d_in[15];
    const float* b2    = (const float*)d_in[16];
    const float* clsW  = (const float*)d_in[17];
    const float* clsb  = (const float*)d_in[18];

    int n  = in_sizes[0] / 64;   // 50000
    int E  = in_sizes[1] / 2;    // 800000
    int ET = E + n;

    const int T = 256;
    int warpBlocks = cdiv(n * 32, T);
    int nb = cdiv(n, 512);

    build_in0_kernel<<<warpBlocks, T>>>(x, batch, clab, emb, n);

    // CSR by dst (once; reused for all layers)
    zero_kernel<<<cdiv(n, T), T>>>(n);
    deg_kernel<<<cdiv(ET, T), T>>>(ei, E, ET);
    scan1_kernel<<<nb, 512>>>(n);
    scan2_kernel<<<1, 32>>>(nb, n);
    scan3_kernel<<<nb, 512>>>(n);
    scatter_kernel<<<cdiv(ET, T), T>>>(ei, E, ET);

    dim3 gemm_grid(cdiv(n, 128), 2);

    const float* asl[3] = {as0, as1, as2};
    const float* adl[3] = {ad0, ad1, ad2};
    const float* bl[3]  = {b0, b1, b2};

    for (int l = 0; l < 3; l++) {
        if (l == 0)      gemm_tc_kernel<128, false, 0><<<gemm_grid, T>>>(W0, n);
        else if (l == 1) gemm_tc_kernel<256, true, 1><<<gemm_grid, T>>>(W1, n);
        else             gemm_tc_kernel<256, true, 1><<<gemm_grid, T>>>(W2, n);

        s_kernel<<<warpBlocks, T>>>(asl[l], adl[l], n);
        agg_kernel<<<warpBlocks, T>>>(bl[l], n);
    }

    cls_kernel<<<warpBlocks, T>>>(clsW, clsb, (float*)d_out, n);
}

// round 5
// speedup vs baseline: 3.5920x; 1.2450x over previous
#include <cuda_runtime.h>
#include <cuda_fp16.h>
#include <cstdint>

#define NN 50000
#define EEMAX 800000

// ---------------- scratch (static device globals; no allocation) -------------
__device__ float g_in0[NN * 128];
__device__ __align__(16) __half g_feat[NN * 256];   // fp16 features (OK once mma uses rna-rounded tf32)
__device__ float g_out[NN * 256];                   // activated layer output
__device__ float g_ssrc[NN * 4];
__device__ float g_sdst[NN * 4];
__device__ int   g_deg[NN];
__device__ int   g_cursor[NN];
__device__ int   g_rowptr[NN + 1];
__device__ int   g_csrc[EEMAX + NN];
__device__ int   g_bsum[256];
__device__ int   g_bpre[257];

__device__ __forceinline__ float lrelu(float x, float s) { return x >= 0.f ? x : s * x; }

// round-to-nearest tf32 conversion (raw-bit truncation biases results: R3/R4 failure)
__device__ __forceinline__ uint32_t rna(uint32_t x) {
    uint32_t r;
    asm("cvt.rna.tf32.f32 %0, %1;" : "=r"(r) : "f"(__uint_as_float(x)));
    return r;
}

__device__ __forceinline__ void mma_tf32(float4& c, const uint32_t a[4], const uint32_t b[2]) {
    asm volatile(
        "mma.sync.aligned.m16n8k8.row.col.f32.tf32.tf32.f32 "
        "{%0,%1,%2,%3}, {%4,%5,%6,%7}, {%8,%9}, {%0,%1,%2,%3};"
        : "+f"(c.x), "+f"(c.y), "+f"(c.z), "+f"(c.w)
        : "r"(a[0]), "r"(a[1]), "r"(a[2]), "r"(a[3]), "r"(b[0]), "r"(b[1]));
}

__device__ __forceinline__ void cp16(uint32_t smem_dst, const void* gsrc, int src_bytes) {
    asm volatile("cp.async.ca.shared.global [%0], [%1], 16, %2;\n"
                 :: "r"(smem_dst), "l"(gsrc), "r"(src_bytes));
}

__device__ __forceinline__ void edge_sd(const int* __restrict__ ei, int e, int E, int& s, int& d) {
    if (e < E) { s = ei[e]; d = ei[E + e]; }
    else       { s = e - E; d = e - E; }   // appended self-loops
}

// ---------------- layer-0 input build: in0 = [x | emb[class_label[batch]]] ---
__global__ void build_in0_kernel(const float* __restrict__ x,
                                 const int* __restrict__ batch,
                                 const int* __restrict__ clab,
                                 const float* __restrict__ emb, int n) {
    int gt = blockIdx.x * blockDim.x + threadIdx.x;
    int node = gt >> 5, lane = gt & 31;
    if (node >= n) return;
    float4* dst = reinterpret_cast<float4*>(g_in0 + (size_t)node * 128);
    if (lane < 16) {
        dst[lane] = reinterpret_cast<const float4*>(x + (size_t)node * 64)[lane];
    } else {
        int c = clab[batch[node]];
        dst[lane] = reinterpret_cast<const float4*>(emb + (size_t)c * 64)[lane - 16];
    }
}

// ---------------- tensor-core GEMM (tf32 rna, cp.async 2-stage) --------------
// g_feat[M,256](fp16) = A[M,K] @ W[256,K]^T
// BM=128, BN=128, BK=32, 256 threads = 8 warps (4x2), warp tile 32x64.
#define SMS (128 * 36)

template <int K, int SRC>
__global__ void __launch_bounds__(256, 2) gemm_tc_kernel(const float* __restrict__ Wm, int M) {
    constexpr int NT = K / 32;
    extern __shared__ float sm[];
    float* As = sm;                // [2][128][36]
    float* Bs = sm + 2 * SMS;      // [2][128][36]
    const float* __restrict__ A = (SRC == 0) ? g_in0 : g_out;

    const int tid = threadIdx.x;
    const int warp = tid >> 5, lane = tid & 31;
    const int wm = warp >> 1;          // 0..3
    const int wn = warp & 1;           // 0..1
    const int rowBase = blockIdx.x * 128;
    const int colBase = blockIdx.y * 128;

    const uint32_t sbase = (uint32_t)__cvta_generic_to_shared(sm);

    float4 c[2][8];
#pragma unroll
    for (int i = 0; i < 2; i++)
#pragma unroll
        for (int j = 0; j < 8; j++) c[i][j] = make_float4(0.f, 0.f, 0.f, 0.f);

    auto issue = [&](int t) {
        const int buf = t & 1;
        const int k0 = t * 32;
#pragma unroll
        for (int i = 0; i < 4; i++) {
            int f = tid + i * 256;
            int r = f >> 3, cc = (f & 7) * 4;
            int gr = rowBase + r;
            uint32_t da = sbase + (uint32_t)(buf * SMS + r * 36 + cc) * 4u;
            const float* sa = A + (size_t)gr * K + k0 + cc;
            cp16(da, sa, (gr < M) ? 16 : 0);
        }
#pragma unroll
        for (int i = 0; i < 4; i++) {
            int f = tid + i * 256;
            int r = f >> 3, cc = (f & 7) * 4;
            uint32_t db = sbase + (uint32_t)((2 + buf) * SMS + r * 36 + cc) * 4u;
            const float* sb = Wm + (size_t)(colBase + r) * K + k0 + cc;
            cp16(db, sb, 16);
        }
        asm volatile("cp.async.commit_group;\n" ::);
    };

    issue(0);

#pragma unroll 1
    for (int t = 0; t < NT; t++) {
        if (t + 1 < NT) {
            issue(t + 1);
            asm volatile("cp.async.wait_group 1;\n" ::);
        } else {
            asm volatile("cp.async.wait_group 0;\n" ::);
        }
        __syncthreads();
        const int buf = t & 1;
        const uint32_t* Ab = reinterpret_cast<const uint32_t*>(As + buf * SMS);
        const uint32_t* Bb = reinterpret_cast<const uint32_t*>(Bs + buf * SMS);
#pragma unroll
        for (int ks = 0; ks < 4; ks++) {
            const int kc = ks * 8 + (lane & 3);
            uint32_t bfr[8][2];
#pragma unroll
            for (int j = 0; j < 8; j++) {
                int cn = wn * 64 + j * 8 + (lane >> 2);
                bfr[j][0] = rna(Bb[cn * 36 + kc]);
                bfr[j][1] = rna(Bb[cn * 36 + kc + 4]);
            }
            uint32_t afr[2][4];
#pragma unroll
            for (int i = 0; i < 2; i++) {
                int r = wm * 32 + i * 16 + (lane >> 2);
                afr[i][0] = rna(Ab[r * 36 + kc]);
                afr[i][1] = rna(Ab[(r + 8) * 36 + kc]);
                afr[i][2] = rna(Ab[r * 36 + kc + 4]);
                afr[i][3] = rna(Ab[(r + 8) * 36 + kc + 4]);
            }
#pragma unroll
            for (int i = 0; i < 2; i++)
#pragma unroll
                for (int j = 0; j < 8; j++) mma_tf32(c[i][j], afr[i], bfr[j]);
        }
        __syncthreads();
    }

    // epilogue: fp16 store to g_feat[M,256]
#pragma unroll
    for (int i = 0; i < 2; i++) {
#pragma unroll
        for (int j = 0; j < 8; j++) {
            int row0 = rowBase + wm * 32 + i * 16 + (lane >> 2);
            int coln = colBase + wn * 64 + j * 8 + 2 * (lane & 3);
            if (row0 < M)
                *reinterpret_cast<__half2*>(g_feat + (size_t)row0 * 256 + coln) =
                    __floats2half2_rn(c[i][j].x, c[i][j].y);
            if (row0 + 8 < M)
                *reinterpret_cast<__half2*>(g_feat + (size_t)(row0 + 8) * 256 + coln) =
                    __floats2half2_rn(c[i][j].z, c[i][j].w);
        }
    }
}

// ---------------- per-node attention scores (fp16 features) ------------------
__global__ void s_kernel(const float* __restrict__ asrc, const float* __restrict__ adst, int n) {
    int gt = blockIdx.x * blockDim.x + threadIdx.x;
    int node = gt >> 5, lane = gt & 31;
    if (node >= n) return;
    uint4 p = *reinterpret_cast<const uint4*>(g_feat + (size_t)node * 256 + lane * 8);
    const __half2* h2 = reinterpret_cast<const __half2*>(&p);
    float av[8], dv[8];
    *reinterpret_cast<float4*>(av)     = reinterpret_cast<const float4*>(asrc + lane * 8)[0];
    *reinterpret_cast<float4*>(av + 4) = reinterpret_cast<const float4*>(asrc + lane * 8)[1];
    *reinterpret_cast<float4*>(dv)     = reinterpret_cast<const float4*>(adst + lane * 8)[0];
    *reinterpret_cast<float4*>(dv + 4) = reinterpret_cast<const float4*>(adst + lane * 8)[1];
    float ss = 0.f, sd = 0.f;
#pragma unroll
    for (int j = 0; j < 4; j++) {
        float2 hf = __half22float2(h2[j]);
        ss += hf.x * av[2 * j] + hf.y * av[2 * j + 1];
        sd += hf.x * dv[2 * j] + hf.y * dv[2 * j + 1];
    }
#pragma unroll
    for (int off = 4; off; off >>= 1) {
        ss += __shfl_xor_sync(0xffffffffu, ss, off);
        sd += __shfl_xor_sync(0xffffffffu, sd, off);
    }
    if ((lane & 7) == 0) {
        g_ssrc[node * 4 + (lane >> 3)] = ss;
        g_sdst[node * 4 + (lane >> 3)] = sd;
    }
}

// ---------------- CSR build --------------------------------------------------
__global__ void zero_kernel(int n) {
    int i = blockIdx.x * blockDim.x + threadIdx.x;
    if (i < n) { g_deg[i] = 0; g_cursor[i] = 0; }
}

__global__ void deg_kernel(const int* __restrict__ ei, int E, int ET) {
    int e = blockIdx.x * blockDim.x + threadIdx.x;
    if (e >= ET) return;
    int s, d; edge_sd(ei, e, E, s, d);
    atomicAdd(&g_deg[d], 1);
}

__global__ void scan1_kernel(int n) {
    __shared__ int sh[512];
    int i = blockIdx.x * 512 + threadIdx.x;
    int v = (i < n) ? g_deg[i] : 0;
    sh[threadIdx.x] = v;
    __syncthreads();
#pragma unroll
    for (int off = 1; off < 512; off <<= 1) {
        int t = (threadIdx.x >= off) ? sh[threadIdx.x - off] : 0;
        __syncthreads();
        if (threadIdx.x >= off) sh[threadIdx.x] += t;
        __syncthreads();
    }
    if (i < n) g_rowptr[i] = sh[threadIdx.x] - v;
    if (threadIdx.x == 511) g_bsum[blockIdx.x] = sh[511];
}

__global__ void scan2_kernel(int nb, int n) {
    if (threadIdx.x == 0 && blockIdx.x == 0) {
        int acc = 0;
        for (int j = 0; j < nb; j++) { g_bpre[j] = acc; acc += g_bsum[j]; }
        g_rowptr[n] = acc;
    }
}

__global__ void scan3_kernel(int n) {
    int i = blockIdx.x * 512 + threadIdx.x;
    if (i < n) g_rowptr[i] += g_bpre[blockIdx.x];
}

__global__ void scatter_kernel(const int* __restrict__ ei, int E, int ET) {
    int e = blockIdx.x * blockDim.x + threadIdx.x;
    if (e >= ET) return;
    int s, d; edge_sd(ei, e, E, s, d);
    int pos = g_rowptr[d] + atomicAdd(&g_cursor[d], 1);
    g_csrc[pos] = s;
}

// ---------------- fused softmax + aggregation + bias + activation ------------
__global__ void agg_kernel(const float* __restrict__ b, int n) {
    int gt = blockIdx.x * blockDim.x + threadIdx.x;
    int dst = gt >> 5, lane = gt & 31;
    if (dst >= n) return;
    const int beg = g_rowptr[dst], end = g_rowptr[dst + 1];
    const float4 sd4 = *reinterpret_cast<const float4*>(g_sdst + (size_t)dst * 4);

    // phase 1: segment max per head
    const float NEG = __int_as_float(0xff800000);
    float4 mx = make_float4(NEG, NEG, NEG, NEG);
    for (int i = beg + lane; i < end; i += 32) {
        int s = g_csrc[i];
        float4 ss = *reinterpret_cast<const float4*>(g_ssrc + (size_t)s * 4);
        mx.x = fmaxf(mx.x, lrelu(ss.x + sd4.x, 0.2f));
        mx.y = fmaxf(mx.y, lrelu(ss.y + sd4.y, 0.2f));
        mx.z = fmaxf(mx.z, lrelu(ss.z + sd4.z, 0.2f));
        mx.w = fmaxf(mx.w, lrelu(ss.w + sd4.w, 0.2f));
    }
#pragma unroll
    for (int off = 16; off; off >>= 1) {
        mx.x = fmaxf(mx.x, __shfl_xor_sync(0xffffffffu, mx.x, off));
        mx.y = fmaxf(mx.y, __shfl_xor_sync(0xffffffffu, mx.y, off));
        mx.z = fmaxf(mx.z, __shfl_xor_sync(0xffffffffu, mx.z, off));
        mx.w = fmaxf(mx.w, __shfl_xor_sync(0xffffffffu, mx.w, off));
    }

    // phase 2: segment sum of exp
    float4 den = make_float4(0.f, 0.f, 0.f, 0.f);
    for (int i = beg + lane; i < end; i += 32) {
        int s = g_csrc[i];
        float4 ss = *reinterpret_cast<const float4*>(g_ssrc + (size_t)s * 4);
        den.x += __expf(lrelu(ss.x + sd4.x, 0.2f) - mx.x);
        den.y += __expf(lrelu(ss.y + sd4.y, 0.2f) - mx.y);
        den.z += __expf(lrelu(ss.z + sd4.z, 0.2f) - mx.z);
        den.w += __expf(lrelu(ss.w + sd4.w, 0.2f) - mx.w);
    }
#pragma unroll
    for (int off = 16; off; off >>= 1) {
        den.x += __shfl_xor_sync(0xffffffffu, den.x, off);
        den.y += __shfl_xor_sync(0xffffffffu, den.y, off);
        den.z += __shfl_xor_sync(0xffffffffu, den.z, off);
        den.w += __shfl_xor_sync(0xffffffffu, den.w, off);
    }

    const int h = lane >> 3;
    float mh  = (h & 2) ? ((h & 1) ? mx.w : mx.z) : ((h & 1) ? mx.y : mx.x);
    float dh  = (h & 2) ? ((h & 1) ? den.w : den.z) : ((h & 1) ? den.y : den.x);
    float sdh = (h & 2) ? ((h & 1) ? sd4.w : sd4.z) : ((h & 1) ? sd4.y : sd4.x);
    const float invd = 1.f / (dh + 1e-16f);

    // phase 3: weighted aggregation over fp16 features, 2-edge unroll
    float2 acc[4];
#pragma unroll
    for (int j = 0; j < 4; j++) acc[j] = make_float2(0.f, 0.f);

    int i = beg;
    for (; i + 1 < end; i += 2) {
        int s0 = g_csrc[i], s1 = g_csrc[i + 1];
        float w0 = __expf(lrelu(g_ssrc[(size_t)s0 * 4 + h] + sdh, 0.2f) - mh) * invd;
        float w1 = __expf(lrelu(g_ssrc[(size_t)s1 * 4 + h] + sdh, 0.2f) - mh) * invd;
        uint4 p0 = *reinterpret_cast<const uint4*>(g_feat + (size_t)s0 * 256 + lane * 8);
        uint4 p1 = *reinterpret_cast<const uint4*>(g_feat + (size_t)s1 * 256 + lane * 8);
        const __half2* q0 = reinterpret_cast<const __half2*>(&p0);
        const __half2* q1 = reinterpret_cast<const __half2*>(&p1);
#pragma unroll
        for (int j = 0; j < 4; j++) {
            float2 f0 = __half22float2(q0[j]);
            float2 f1 = __half22float2(q1[j]);
            acc[j].x += w0 * f0.x + w1 * f1.x;
            acc[j].y += w0 * f0.y + w1 * f1.y;
        }
    }
    if (i < end) {
        int s0 = g_csrc[i];
        float w0 = __expf(lrelu(g_ssrc[(size_t)s0 * 4 + h] + sdh, 0.2f) - mh) * invd;
        uint4 p0 = *reinterpret_cast<const uint4*>(g_feat + (size_t)s0 * 256 + lane * 8);
        const __half2* q0 = reinterpret_cast<const __half2*>(&p0);
#pragma unroll
        for (int j = 0; j < 4; j++) {
            float2 f0 = __half22float2(q0[j]);
            acc[j].x += w0 * f0.x;
            acc[j].y += w0 * f0.y;
        }
    }

    const float4 b0 = reinterpret_cast<const float4*>(b)[lane * 2];
    const float4 b1 = reinterpret_cast<const float4*>(b)[lane * 2 + 1];
    float4* op = reinterpret_cast<float4*>(g_out + (size_t)dst * 256 + lane * 8);
    op[0] = make_float4(lrelu(acc[0].x + b0.x, 0.01f), lrelu(acc[0].y + b0.y, 0.01f),
                        lrelu(acc[1].x + b0.z, 0.01f), lrelu(acc[1].y + b0.w, 0.01f));
    op[1] = make_float4(lrelu(acc[2].x + b1.x, 0.01f), lrelu(acc[2].y + b1.y, 0.01f),
                        lrelu(acc[3].x + b1.z, 0.01f), lrelu(acc[3].y + b1.w, 0.01f));
}

// ---------------- classifier (input already activated) -----------------------
__global__ void cls_kernel(const float* __restrict__ clsW, const float* __restrict__ clsb,
                           float* __restrict__ y, int n) {
    int gt = blockIdx.x * blockDim.x + threadIdx.x;
    int node = gt >> 5, lane = gt & 31;
    if (node >= n) return;
    const float4* o4 = reinterpret_cast<const float4*>(g_out + (size_t)node * 256 + lane * 8);
    const float4* w4 = reinterpret_cast<const float4*>(clsW + lane * 8);
    float sum = 0.f;
#pragma unroll
    for (int i = 0; i < 2; i++) {
        float4 v = o4[i], w = w4[i];
        sum += v.x * w.x + v.y * w.y + v.z * w.z + v.w * w.w;
    }
#pragma unroll
    for (int off = 16; off; off >>= 1) sum += __shfl_xor_sync(0xffffffffu, sum, off);
    if (lane == 0) y[node] = sum + clsb[0];
}

static inline int cdiv(int a, int b) { return (a + b - 1) / b; }

extern "C" void kernel_launch(void* const* d_in, const int* in_sizes, int n_in,
                              void* d_out, int out_size) {
    const float* x     = (const float*)d_in[0];
    const int*   ei    = (const int*)d_in[1];
    const int*   batch = (const int*)d_in[2];
    const int*   clab  = (const int*)d_in[3];
    const float* emb   = (const float*)d_in[4];
    const float* W0    = (const float*)d_in[5];
    const float* as0   = (const float*)d_in[6];
    const float* ad0   = (const float*)d_in[7];
    const float* b0    = (const float*)d_in[8];
    const float* W1    = (const float*)d_in[9];
    const float* as1   = (const float*)d_in[10];
    const float* ad1   = (const float*)d_in[11];
    const float* b1    = (const float*)d_in[12];
    const float* W2    = (const float*)d_in[13];
    const float* as2   = (const float*)d_in[14];
    const float* ad2   = (const float*)d_in[15];
    const float* b2    = (const float*)d_in[16];
    const float* clsW  = (const float*)d_in[17];
    const float* clsb  = (const float*)d_in[18];

    int n  = in_sizes[0] / 64;   // 50000
    int E  = in_sizes[1] / 2;    // 800000
    int ET = E + n;

    const int T = 256;
    int warpBlocks = cdiv(n * 32, T);
    int nb = cdiv(n, 512);
    const int smBytes = 4 * SMS * sizeof(float);   // 73728

    static bool attr_done = false;
    if (!attr_done) {
        cudaFuncSetAttribute(gemm_tc_kernel<128, 0>,
                             cudaFuncAttributeMaxDynamicSharedMemorySize, smBytes);
        cudaFuncSetAttribute(gemm_tc_kernel<256, 1>,
                             cudaFuncAttributeMaxDynamicSharedMemorySize, smBytes);
        attr_done = true;
    }

    build_in0_kernel<<<warpBlocks, T>>>(x, batch, clab, emb, n);

    // CSR by dst (reused for all layers)
    zero_kernel<<<cdiv(n, T), T>>>(n);
    deg_kernel<<<cdiv(ET, T), T>>>(ei, E, ET);
    scan1_kernel<<<nb, 512>>>(n);
    scan2_kernel<<<1, 32>>>(nb, n);
    scan3_kernel<<<nb, 512>>>(n);
    scatter_kernel<<<cdiv(ET, T), T>>>(ei, E, ET);

    dim3 gemm_grid(cdiv(n, 128), 2);

    const float* asl[3] = {as0, as1, as2};
    const float* adl[3] = {ad0, ad1, ad2};
    const float* bl[3]  = {b0, b1, b2};

    for (int l = 0; l < 3; l++) {
        if (l == 0) gemm_tc_kernel<128, 0><<<gemm_grid, T, smBytes>>>(W0, n);
        else        gemm_tc_kernel<256, 1><<<gemm_grid, T, smBytes>>>(l == 1 ? W1 : W2, n);

        s_kernel<<<warpBlocks, T>>>(asl[l], adl[l], n);
        agg_kernel<<<warpBlocks, T>>>(bl[l], n);
    }

    cls_kernel<<<warpBlocks, T>>>(clsW, clsb, (float*)d_out, n);
}